// round 13
// baseline (speedup 1.0000x reference)
#include <cuda_runtime.h>
#include <math.h>
#include <stdint.h>

// ChamferLoss via exact pruned NN, v9: wide phase-1 seed + single radius shot,
// NO per-bucket vote loops (they were the serial bottleneck, R12 post-mortem).
// batch=64, k=2048 2-D points (x = cols [0,2048), y = cols [2048,4096)).
// 256 fixed bins over [-8,8). Phase-1 scans [bl-2,bh+2] contiguously; then a
// per-lane NN-radius bound (saturating f2i handles the INF fallback) gives a
// covering bucket range via one redux; extensions are two contiguous loops.
// Exact: scanned set provably contains each query's NN witness (x-window
// bound; clamped edge bins keep one-sided containment) -> bitwise equal to
// brute force, scatter-order invariant. Deterministic: results by original
// index, fixed-order sums, fused last-block finalize.

#define K        2048
#define BATCH    64
#define THREADS  1024
#define NWARPS   32
#define PPT      2                  // points per thread per side (sort phase)
#define NBINS    256
#define BPL      (NBINS / 32)       // bins per lane in prefix (8)
#define NBLOCKS  (2 * BATCH)
#define XMIN     (-8.0f)
#define INVW     16.0f              // NBINS / 16
#define WB       0.0625f            // bucket width

#define SMEM_D_BYTES   (K * 16)     // float4: 32 KB
#define SMEM_Q_BYTES   (K * 8)      // float2: 16 KB
#define SMEM_QI_BYTES  (K * 2)      // short:   4 KB
#define DYN_SMEM       (SMEM_D_BYTES + SMEM_Q_BYTES + SMEM_QI_BYTES)

__device__ float g_partials[NBLOCKS];
__device__ unsigned int g_count = 0;

__global__ __launch_bounds__(THREADS, 1)
void chamfer_nn_kernel(const float* __restrict__ pred,
                       const float* __restrict__ targ,
                       float* __restrict__ out)
{
    extern __shared__ unsigned char dynsmem[];
    float4* shD  = (float4*)dynsmem;                              // sorted DB (x,y,x2+y2,0)
    float2* shQ  = (float2*)(dynsmem + SMEM_D_BYTES);             // sorted queries
    short*  shQi = (short*)(dynsmem + SMEM_D_BYTES + SMEM_Q_BYTES);

    __shared__ int   cntD[NBINS], cntQ[NBINS];     // histogram -> scatter cursors
    __shared__ int   offD[NBINS + 1];
    __shared__ float red[NWARPS];
    __shared__ int   lastflag;

    const int bx    = blockIdx.x;
    const int batch = bx >> 1;
    const int dir   = bx & 1;
    const int tid   = threadIdx.x;
    const int wg    = tid >> 5, lane = tid & 31;

    const float* q_base = (dir == 0 ? pred : targ) + batch * (2 * K);
    const float* d_base = (dir == 0 ? targ : pred) + batch * (2 * K);

    // ---- Load both sides (coalesced); fixed bucket range ----
    float Dx[PPT], Dy[PPT], Qx[PPT], Qy[PPT];
    #pragma unroll
    for (int r = 0; r < PPT; ++r) {
        int j = r * THREADS + tid;
        Dx[r] = d_base[j];  Dy[r] = d_base[j + K];
        Qx[r] = q_base[j];  Qy[r] = q_base[j + K];
    }

    if (tid < NBINS) { cntD[tid] = 0; cntQ[tid] = 0; }
    __syncthreads();

    int bD[PPT], bQ[PPT];
    #pragma unroll
    for (int r = 0; r < PPT; ++r) {
        bD[r] = min(NBINS - 1, max(0, (int)((Dx[r] - XMIN) * INVW)));
        atomicAdd(&cntD[bD[r]], 1);
        bQ[r] = min(NBINS - 1, max(0, (int)((Qx[r] - XMIN) * INVW)));
        atomicAdd(&cntQ[bQ[r]], 1);
    }
    __syncthreads();

    // ---- Exclusive prefix over 256 bins (warp 0: D + offD; warp 1: Q) ----
    if (wg < 2) {
        int* cnt = (wg == 0) ? cntD : cntQ;
        int c[BPL], s = 0;
        #pragma unroll
        for (int i = 0; i < BPL; ++i) { c[i] = cnt[lane * BPL + i]; s += c[i]; }
        int e = s;
        #pragma unroll
        for (int o = 1; o < 32; o <<= 1) {
            int n = __shfl_up_sync(0xFFFFFFFF, e, o);
            if (lane >= o) e += n;
        }
        int run = e - s;
        #pragma unroll
        for (int i = 0; i < BPL; ++i) {
            if (wg == 0) offD[lane * BPL + i] = run;
            cnt[lane * BPL + i] = run;
            run += c[i];
        }
        if (wg == 0 && lane == 31) offD[NBINS] = e;   // = K
    }
    __syncthreads();

    // ---- Scatter into bucket order ----
    #pragma unroll
    for (int r = 0; r < PPT; ++r) {
        int p = atomicAdd(&cntD[bD[r]], 1);
        shD[p] = make_float4(Dx[r], Dy[r], fmaf(Dx[r], Dx[r], Dy[r] * Dy[r]), 0.0f);
        p = atomicAdd(&cntQ[bQ[r]], 1);
        shQ[p]  = make_float2(Qx[r], Qy[r]);
        shQi[p] = (short)(r * THREADS + tid);
    }
    __syncthreads();

    // ---- Scan: warp wg owns 64 consecutive sorted queries, 2 per lane ----
    const int pairidx = wg * 32 + lane;
    const float4 qq = *(const float4*)&shQ[2 * pairidx];
    const short2 qi = ((const short2*)shQi)[pairidx];

    const float ax0 = -2.0f * qq.x, ay0 = -2.0f * qq.y;
    const float ax1 = -2.0f * qq.z, ay1 = -2.0f * qq.w;
    const float q20 = fmaf(qq.x, qq.x, qq.y * qq.y);
    const float q21 = fmaf(qq.z, qq.z, qq.w * qq.w);
    const float qxmn = fminf(qq.x, qq.z);
    const float qxmx = fmaxf(qq.x, qq.z);

    int b0 = min(NBINS - 1, max(0, (int)((qq.x - XMIN) * INVW)));
    int b1 = min(NBINS - 1, max(0, (int)((qq.z - XMIN) * INVW)));
    const int bl = __reduce_min_sync(0xFFFFFFFF, min(b0, b1));
    const int bh = __reduce_max_sync(0xFFFFFFFF, max(b0, b1));
    const int p1l = max(bl - 2, 0);
    const int p1h = min(bh + 2, NBINS - 1);

    float mnA0 = INFINITY, mnB0 = INFINITY;
    float mnA1 = INFINITY, mnB1 = INFINITY;

    // Phase 1: wide contiguous neighborhood [bl-2, bh+2] (broadcast LDS.128)
    {
        const int lo = offD[p1l], hi = offD[p1h + 1];
        int idx = lo;
        for (; idx + 2 <= hi; idx += 2) {
            float4 t0 = shD[idx], t1 = shD[idx + 1];
            mnA0 = fminf(mnA0, fmaf(ax0, t0.x, fmaf(ay0, t0.y, t0.z)));
            mnA1 = fminf(mnA1, fmaf(ax1, t0.x, fmaf(ay1, t0.y, t0.z)));
            mnB0 = fminf(mnB0, fmaf(ax0, t1.x, fmaf(ay0, t1.y, t1.z)));
            mnB1 = fminf(mnB1, fmaf(ax1, t1.x, fmaf(ay1, t1.y, t1.z)));
        }
        if (idx < hi) {
            float4 t = shD[idx];
            mnA0 = fminf(mnA0, fmaf(ax0, t.x, fmaf(ay0, t.y, t.z)));
            mnA1 = fminf(mnA1, fmaf(ax1, t.x, fmaf(ay1, t.y, t.z)));
        }
    }

    // Single radius shot: per-lane covering bucket range, one redux each.
    // INF bound -> f2i saturates -> full range (exact fallback for free).
    {
        const float m2 = fmaxf(fmaxf(q20 + fminf(mnA0, mnB0),
                                     q21 + fminf(mnA1, mnB1)), 0.0f);
        const float rr = sqrtf(m2);
        int loi = __float2int_rd((qxmn - rr - XMIN) * INVW);
        int hii = __float2int_rd((qxmx + rr - XMIN) * INVW);
        int loB = max(0,         __reduce_min_sync(0xFFFFFFFF, loi));
        int hiB = min(NBINS - 1, __reduce_max_sync(0xFFFFFFFF, hii));

        // Left extension [loB, p1l): contiguous, usually empty.
        {
            const int lo = offD[min(loB, p1l)], hi = offD[p1l];
            int idx = lo;
            for (; idx + 2 <= hi; idx += 2) {
                float4 t0 = shD[idx], t1 = shD[idx + 1];
                mnA0 = fminf(mnA0, fmaf(ax0, t0.x, fmaf(ay0, t0.y, t0.z)));
                mnA1 = fminf(mnA1, fmaf(ax1, t0.x, fmaf(ay1, t0.y, t0.z)));
                mnB0 = fminf(mnB0, fmaf(ax0, t1.x, fmaf(ay0, t1.y, t1.z)));
                mnB1 = fminf(mnB1, fmaf(ax1, t1.x, fmaf(ay1, t1.y, t1.z)));
            }
            if (idx < hi) {
                float4 t = shD[idx];
                mnA0 = fminf(mnA0, fmaf(ax0, t.x, fmaf(ay0, t.y, t.z)));
                mnA1 = fminf(mnA1, fmaf(ax1, t.x, fmaf(ay1, t.y, t.z)));
            }
        }
        // Right extension (p1h, hiB]: contiguous, usually empty.
        {
            const int lo = offD[p1h + 1], hi = offD[max(hiB, p1h) + 1];
            int idx = lo;
            for (; idx + 2 <= hi; idx += 2) {
                float4 t0 = shD[idx], t1 = shD[idx + 1];
                mnA0 = fminf(mnA0, fmaf(ax0, t0.x, fmaf(ay0, t0.y, t0.z)));
                mnA1 = fminf(mnA1, fmaf(ax1, t0.x, fmaf(ay1, t0.y, t0.z)));
                mnB0 = fminf(mnB0, fmaf(ax0, t1.x, fmaf(ay0, t1.y, t1.z)));
                mnB1 = fminf(mnB1, fmaf(ax1, t1.x, fmaf(ay1, t1.y, t1.z)));
            }
            if (idx < hi) {
                float4 t = shD[idx];
                mnA0 = fminf(mnA0, fmaf(ax0, t.x, fmaf(ay0, t.y, t.z)));
                mnA1 = fminf(mnA1, fmaf(ax1, t.x, fmaf(ay1, t.y, t.z)));
            }
        }
    }

    const float res0 = sqrtf(fmaxf(q20 + fminf(mnA0, mnB0), 0.0f));
    const float res1 = sqrtf(fmaxf(q21 + fminf(mnA1, mnB1), 0.0f));
    __syncthreads();     // all warps done reading shD/shQ before overwrite

    // ---- Scatter results to original order (reuse shD), fixed-order sum ----
    float* rslt = (float*)shD;
    rslt[qi.x] = res0;
    rslt[qi.y] = res1;
    __syncthreads();

    float s = rslt[tid] + rslt[tid + THREADS];
    #pragma unroll
    for (int o = 16; o > 0; o >>= 1)
        s += __shfl_xor_sync(0xFFFFFFFF, s, o);
    if (lane == 0) red[wg] = s;
    __syncthreads();

    float v = 0.0f;
    if (tid < 32) {
        v = red[tid];
        #pragma unroll
        for (int o = 16; o > 0; o >>= 1)
            v += __shfl_down_sync(0xFFFFFFFF, v, o);
    }

    // ---- Fused finalize: last block sums the 128 partials ----
    if (tid == 0) {
        g_partials[bx] = v;
        __threadfence();
        unsigned old = atomicAdd(&g_count, 1u);
        lastflag = (old == NBLOCKS - 1);
    }
    __syncthreads();
    if (lastflag && tid < 32) {
        volatile float* gp = g_partials;
        float t = 0.0f;
        #pragma unroll
        for (int i = 0; i < NBLOCKS / 32; ++i)
            t += gp[i * 32 + tid];
        #pragma unroll
        for (int o = 16; o > 0; o >>= 1)
            t += __shfl_down_sync(0xFFFFFFFF, t, o);
        if (tid == 0) {
            out[0] = t * (1.0f / ((float)K * (float)BATCH));
            g_count = 0;   // reset for next graph replay
        }
    }
}

extern "C" void kernel_launch(void* const* d_in, const int* in_sizes, int n_in,
                              void* d_out, int out_size)
{
    const float* pred = (const float*)d_in[0];
    const float* targ = (const float*)d_in[1];
    float* out = (float*)d_out;

    cudaFuncSetAttribute(chamfer_nn_kernel,
                         cudaFuncAttributeMaxDynamicSharedMemorySize, DYN_SMEM);
    chamfer_nn_kernel<<<NBLOCKS, THREADS, DYN_SMEM>>>(pred, targ, out);
}

// round 16
// speedup vs baseline: 1.0040x; 1.0040x over previous
#include <cuda_runtime.h>
#include <math.h>
#include <stdint.h>

// ChamferLoss via exact pruned NN, v10b = R14 with ALIGNED smem offsets
// (R15 failed on a 16B-misaligned float4 query load: OFF_Q was 8 mod 16).
// Scan inner loop packed as fma.rn.f32x2 over candidate PAIRS:
// one pair = 2 LDS + 4 FFMA2 + 4 FMNMX vs 17 scalar slots.
// batch=64, k=2048 2-D points (x = cols [0,2048), y = cols [2048,4096)).
// Sorted D pair-packed SoA: float4 (x0,x1,y0,y1) + float2 (z0,z1); window
// ends rounded to pairs; sentinel pair (z=1e30) keeps loops pair-pure and
// the scanned set an exact covering superset == brute force bitwise.
// Deterministic: results by original index, fixed-order sums, fused finalize.

#define K        2048
#define BATCH    64
#define THREADS  1024
#define NWARPS   32
#define EPT      2
#define NBINS    128
#define NBLOCKS  (2 * BATCH)
#define NPAIRS   (K / 2 + 1)        // +1 pair of sentinels

#define ALIGN16(x)     (((x) + 15) & ~15)
#define SMEM_XY_BYTES  (NPAIRS * 16)
#define SMEM_ZZ_BYTES  (NPAIRS * 8)
#define SMEM_Q_BYTES   (K * 8)
#define SMEM_QI_BYTES  (K * 2)
#define OFF_ZZ   ALIGN16(SMEM_XY_BYTES)
#define OFF_Q    ALIGN16(OFF_ZZ + SMEM_ZZ_BYTES)
#define OFF_QI   ALIGN16(OFF_Q + SMEM_Q_BYTES)
#define DYN_SMEM (OFF_QI + SMEM_QI_BYTES)

__device__ float g_partials[NBLOCKS];
__device__ unsigned int g_count = 0;

__device__ __forceinline__ uint32_t smem_u32(const void* p) {
    uint32_t a;
    asm("{ .reg .u64 t; cvta.to.shared.u64 t, %1; cvt.u32.u64 %0, t; }"
        : "=r"(a) : "l"(p));
    return a;
}

__global__ __launch_bounds__(THREADS, 1)
void chamfer_nn_kernel(const float* __restrict__ pred,
                       const float* __restrict__ targ,
                       float* __restrict__ out)
{
    extern __shared__ unsigned char dynsmem[];
    float*  shXY = (float*)dynsmem;                    // pair-packed (x0,x1,y0,y1)
    float*  shZZ = (float*)(dynsmem + OFF_ZZ);         // pair-packed (z0,z1)
    float2* shQ  = (float2*)(dynsmem + OFF_Q);         // sorted queries (16B-aligned)
    short*  shQi = (short*)(dynsmem + OFF_QI);         // original query index

    __shared__ int   cntD[NBINS], cntQ[NBINS];
    __shared__ int   offD[NBINS + 1];
    __shared__ float red[THREADS];
    __shared__ int   lastflag;

    const int bx    = blockIdx.x;
    const int batch = bx >> 1;
    const int dir   = bx & 1;
    const int tid   = threadIdx.x;
    const int wg    = tid >> 5, lane = tid & 31;

    const float* q_base = (dir == 0 ? pred : targ) + batch * (2 * K);
    const float* d_base = (dir == 0 ? targ : pred) + batch * (2 * K);

    // ---- Load both sides; block min/max of x over BOTH sides ----
    float Dx[EPT], Dy[EPT], Qx[EPT], Qy[EPT];
    float lmin = INFINITY, lmax = -INFINITY;
    #pragma unroll
    for (int r = 0; r < EPT; ++r) {
        int j = r * THREADS + tid;
        Dx[r] = d_base[j];  Dy[r] = d_base[j + K];
        Qx[r] = q_base[j];  Qy[r] = q_base[j + K];
        lmin = fminf(lmin, fminf(Dx[r], Qx[r]));
        lmax = fmaxf(lmax, fmaxf(Dx[r], Qx[r]));
    }
    red[tid] = lmin; __syncthreads();
    for (int o = THREADS / 2; o > 0; o >>= 1) {
        if (tid < o) red[tid] = fminf(red[tid], red[tid + o]);
        __syncthreads();
    }
    const float xmin = red[0]; __syncthreads();
    red[tid] = lmax; __syncthreads();
    for (int o = THREADS / 2; o > 0; o >>= 1) {
        if (tid < o) red[tid] = fmaxf(red[tid], red[tid + o]);
        __syncthreads();
    }
    const float xmax = red[0]; __syncthreads();

    const float inv = (float)NBINS / ((xmax - xmin) * 1.000001f + 1e-30f);
    const float w   = 1.0f / inv;

    // ---- Histograms ----
    if (tid < NBINS) { cntD[tid] = 0; cntQ[tid] = 0; }
    __syncthreads();
    int bD[EPT], bQ[EPT];
    #pragma unroll
    for (int r = 0; r < EPT; ++r) {
        bD[r] = min(NBINS - 1, max(0, (int)((Dx[r] - xmin) * inv)));
        atomicAdd(&cntD[bD[r]], 1);
        bQ[r] = min(NBINS - 1, max(0, (int)((Qx[r] - xmin) * inv)));
        atomicAdd(&cntQ[bQ[r]], 1);
    }
    __syncthreads();

    // ---- Exclusive prefix (warp 0: D -> offD + cursors; warp 1: Q) ----
    if (wg < 2) {
        int* cnt = (wg == 0) ? cntD : cntQ;
        int c0 = cnt[lane * 4 + 0], c1 = cnt[lane * 4 + 1];
        int c2 = cnt[lane * 4 + 2], c3 = cnt[lane * 4 + 3];
        int s = c0 + c1 + c2 + c3, e = s;
        #pragma unroll
        for (int o = 1; o < 32; o <<= 1) {
            int n = __shfl_up_sync(0xFFFFFFFF, e, o);
            if (lane >= o) e += n;
        }
        int excl = e - s;
        if (wg == 0) {
            offD[lane * 4 + 0] = excl;
            offD[lane * 4 + 1] = excl + c0;
            offD[lane * 4 + 2] = excl + c0 + c1;
            offD[lane * 4 + 3] = excl + c0 + c1 + c2;
            if (lane == 31) offD[NBINS] = e;
        }
        cnt[lane * 4 + 0] = excl;
        cnt[lane * 4 + 1] = excl + c0;
        cnt[lane * 4 + 2] = excl + c0 + c1;
        cnt[lane * 4 + 3] = excl + c0 + c1 + c2;
    }
    __syncthreads();

    // ---- Scatter into bucket order (pair-packed layout) + sentinels ----
    #pragma unroll
    for (int r = 0; r < EPT; ++r) {
        int p = atomicAdd(&cntD[bD[r]], 1);
        int pr = p >> 1, half = p & 1;
        shXY[pr * 4 + half]     = Dx[r];
        shXY[pr * 4 + 2 + half] = Dy[r];
        shZZ[p] = fmaf(Dx[r], Dx[r], Dy[r] * Dy[r]);
        p = atomicAdd(&cntQ[bQ[r]], 1);
        shQ[p]  = make_float2(Qx[r], Qy[r]);
        shQi[p] = (short)(r * THREADS + tid);
    }
    if (tid == 0) {           // sentinel pair at indices K, K+1 (finite, huge)
        shXY[(K / 2) * 4 + 0] = 1e15f;  shXY[(K / 2) * 4 + 1] = 1e15f;
        shXY[(K / 2) * 4 + 2] = 0.0f;   shXY[(K / 2) * 4 + 3] = 0.0f;
        shZZ[K] = 1e30f;  shZZ[K + 1] = 1e30f;
    }
    __syncthreads();

    const uint32_t aXY = smem_u32(shXY);
    const uint32_t aZZ = smem_u32(shZZ);

    // ---- Scan: warp wg owns 64 consecutive sorted queries, 2 per lane ----
    const int pairidx = wg * 32 + lane;
    const float4 qq = *(const float4*)&shQ[2 * pairidx];
    const short2 qi = ((const short2*)shQi)[pairidx];

    const float ax0 = -2.0f * qq.x, ay0 = -2.0f * qq.y;
    const float ax1 = -2.0f * qq.z, ay1 = -2.0f * qq.w;
    const float q20 = fmaf(qq.x, qq.x, qq.y * qq.y);
    const float q21 = fmaf(qq.z, qq.z, qq.w * qq.w);
    const float qxmn = fminf(qq.x, qq.z);
    const float qxmx = fmaxf(qq.x, qq.z);

    uint64_t ax0d, ay0d, ax1d, ay1d;      // duplicated packed constants
    asm("mov.b64 %0, {%1, %1};" : "=l"(ax0d) : "f"(ax0));
    asm("mov.b64 %0, {%1, %1};" : "=l"(ay0d) : "f"(ay0));
    asm("mov.b64 %0, {%1, %1};" : "=l"(ax1d) : "f"(ax1));
    asm("mov.b64 %0, {%1, %1};" : "=l"(ay1d) : "f"(ay1));

    int b0 = min(NBINS - 1, max(0, (int)((qq.x - xmin) * inv)));
    int b1 = min(NBINS - 1, max(0, (int)((qq.z - xmin) * inv)));
    const int bl = __reduce_min_sync(0xFFFFFFFF, min(b0, b1));
    const int bh = __reduce_max_sync(0xFFFFFFFF, max(b0, b1));

    float mnA0 = INFINITY, mnB0 = INFINITY;
    float mnA1 = INFINITY, mnB1 = INFINITY;

    // Packed pair body: candidates 2i, 2i+1 vs both queries.
#define PAIR_BODY(i)                                                        \
    do {                                                                    \
        uint64_t xx_, yy_, zz_, t_, v0_, v1_;                               \
        asm("ld.shared.v2.b64 {%0, %1}, [%2];"                              \
            : "=l"(xx_), "=l"(yy_) : "r"(aXY + (unsigned)(i) * 16));        \
        asm("ld.shared.b64 %0, [%1];"                                       \
            : "=l"(zz_) : "r"(aZZ + (unsigned)(i) * 8));                    \
        asm("fma.rn.f32x2 %0, %1, %2, %3;"                                  \
            : "=l"(t_) : "l"(ay0d), "l"(yy_), "l"(zz_));                    \
        asm("fma.rn.f32x2 %0, %1, %2, %3;"                                  \
            : "=l"(v0_) : "l"(ax0d), "l"(xx_), "l"(t_));                    \
        asm("fma.rn.f32x2 %0, %1, %2, %3;"                                  \
            : "=l"(t_) : "l"(ay1d), "l"(yy_), "l"(zz_));                    \
        asm("fma.rn.f32x2 %0, %1, %2, %3;"                                  \
            : "=l"(v1_) : "l"(ax1d), "l"(xx_), "l"(t_));                    \
        float l0_, h0_, l1_, h1_;                                           \
        asm("mov.b64 {%0, %1}, %2;" : "=f"(l0_), "=f"(h0_) : "l"(v0_));     \
        asm("mov.b64 {%0, %1}, %2;" : "=f"(l1_), "=f"(h1_) : "l"(v1_));     \
        mnA0 = fminf(mnA0, l0_);  mnB0 = fminf(mnB0, h0_);                  \
        mnA1 = fminf(mnA1, l1_);  mnB1 = fminf(mnB1, h1_);                  \
    } while (0)

    // Phase 1: contiguous neighborhood [bl-1, bh+1], pair loop, unroll 2.
    {
        const int lo2 = offD[max(bl - 1, 0)] >> 1;
        const int hi2 = (offD[min(bh + 1, NBINS - 1) + 1] + 1) >> 1;
        int i = lo2;
        for (; i + 2 <= hi2; i += 2) { PAIR_BODY(i); PAIR_BODY(i + 1); }
        if (i < hi2) PAIR_BODY(i);
    }

    // Left expansion: per-bucket warp vote (pair loop).
    for (int l = bl - 2; l >= 0; --l) {
        float best = fmaxf(q20 + fminf(mnA0, mnB0), q21 + fminf(mnA1, mnB1));
        float gap  = qxmn - (xmin + (float)(l + 1) * w);
        bool need  = (gap <= 0.0f) || (gap * gap < best);
        if (!__any_sync(0xFFFFFFFF, need)) break;
        const int lo2 = offD[l] >> 1;
        const int hi2 = (offD[l + 1] + 1) >> 1;
        for (int i = lo2; i < hi2; ++i) PAIR_BODY(i);
    }
    // Right expansion.
    for (int r = bh + 2; r < NBINS; ++r) {
        float best = fmaxf(q20 + fminf(mnA0, mnB0), q21 + fminf(mnA1, mnB1));
        float gap  = (xmin + (float)r * w) - qxmx;
        bool need  = (gap <= 0.0f) || (gap * gap < best);
        if (!__any_sync(0xFFFFFFFF, need)) break;
        const int lo2 = offD[r] >> 1;
        const int hi2 = (offD[r + 1] + 1) >> 1;
        for (int i = lo2; i < hi2; ++i) PAIR_BODY(i);
    }
#undef PAIR_BODY

    const float res0 = sqrtf(fmaxf(q20 + fminf(mnA0, mnB0), 0.0f));
    const float res1 = sqrtf(fmaxf(q21 + fminf(mnA1, mnB1), 0.0f));
    __syncthreads();     // all warps done reading D/Q before overwrite

    // ---- Scatter results to original order (reuse shXY), fixed-order sum ----
    float* rslt = (float*)shXY;
    rslt[qi.x] = res0;
    rslt[qi.y] = res1;
    __syncthreads();

    float s = rslt[tid] + rslt[tid + THREADS];
    #pragma unroll
    for (int o = 16; o > 0; o >>= 1)
        s += __shfl_xor_sync(0xFFFFFFFF, s, o);
    if (lane == 0) red[wg] = s;
    __syncthreads();

    float v = 0.0f;
    if (tid < 32) {
        v = red[tid];
        #pragma unroll
        for (int o = 16; o > 0; o >>= 1)
            v += __shfl_down_sync(0xFFFFFFFF, v, o);
    }

    // ---- Fused finalize: last block sums the 128 partials ----
    if (tid == 0) {
        g_partials[bx] = v;
        __threadfence();
        unsigned old = atomicAdd(&g_count, 1u);
        lastflag = (old == NBLOCKS - 1);
    }
    __syncthreads();
    if (lastflag && tid < 32) {
        volatile float* gp = g_partials;
        float t = 0.0f;
        #pragma unroll
        for (int i = 0; i < NBLOCKS / 32; ++i)
            t += gp[i * 32 + tid];
        #pragma unroll
        for (int o = 16; o > 0; o >>= 1)
            t += __shfl_down_sync(0xFFFFFFFF, t, o);
        if (tid == 0) {
            out[0] = t * (1.0f / ((float)K * (float)BATCH));
            g_count = 0;   // reset for next graph replay
        }
    }
}

extern "C" void kernel_launch(void* const* d_in, const int* in_sizes, int n_in,
                              void* d_out, int out_size)
{
    const float* pred = (const float*)d_in[0];
    const float* targ = (const float*)d_in[1];
    float* out = (float*)d_out;

    cudaFuncSetAttribute(chamfer_nn_kernel,
                         cudaFuncAttributeMaxDynamicSharedMemorySize, DYN_SMEM);
    chamfer_nn_kernel<<<NBLOCKS, THREADS, DYN_SMEM>>>(pred, targ, out);
}